// round 7
// baseline (speedup 1.0000x reference)
#include <cuda_runtime.h>
#include <cuda_fp16.h>

#define N_NODES 50000
#define N_EDGES 600000
#define DIM 128
#define OUTD 64

#define PADA 136   // words per row (k-stride); 136 mod 32 = 8 -> conflict-free LDS.64

// ---- scratch (static device globals; no runtime allocation) ----
__device__ __half2   g_msg[N_NODES * 64];   // fp16 messages (128 per node)
__device__ float     g_h[N_NODES * DIM];
__device__ int       g_deg[N_NODES];
__device__ int       g_off[N_NODES];
__device__ int       g_cur[N_NODES];
__device__ int       g_ctr;
__device__ int       g_csr_src[N_EDGES];
__device__ unsigned  g_Bt1[2 * 192 * 128];  // layer-1 weights, tf32, k-permuted, usage order
__device__ unsigned  g_Bt2[2 * 192 * 128];  // layer-2 weights
__device__ unsigned  g_Bp[64 * 128];        // Wp, tf32 (unpermuted)

// ============================ helpers ============================

__device__ __forceinline__ unsigned f2tf32(float f) {
    unsigned u;
    asm("cvt.rna.tf32.f32 %0, %1;" : "=r"(u) : "f"(f));
    return u;
}

__device__ __forceinline__ void mma_tf32(float* c,
                                         unsigned a0, unsigned a1, unsigned a2, unsigned a3,
                                         unsigned b0, unsigned b1) {
    asm volatile(
        "mma.sync.aligned.m16n8k8.row.col.f32.tf32.tf32.f32 "
        "{%0,%1,%2,%3}, {%4,%5,%6,%7}, {%8,%9}, {%0,%1,%2,%3};"
        : "+f"(c[0]), "+f"(c[1]), "+f"(c[2]), "+f"(c[3])
        : "r"(a0), "r"(a1), "r"(a2), "r"(a3), "r"(b0), "r"(b1));
}

// ============================ CSR build ============================

__global__ void zero_deg_kernel() {
    int i = blockIdx.x * blockDim.x + threadIdx.x;
    if (i < N_NODES) g_deg[i] = 0;
    if (i == 0) g_ctr = 0;
}

__global__ void hist_kernel(const int* __restrict__ dst) {
    int e = blockIdx.x * blockDim.x + threadIdx.x;
    if (e < N_EDGES) atomicAdd(&g_deg[dst[e]], 1);
}

// unordered disjoint range claim (aggregation is order-agnostic)
__global__ void offsets_kernel() {
    int i = blockIdx.x * blockDim.x + threadIdx.x;
    if (i < N_NODES) {
        int d = g_deg[i];
        int s = atomicAdd(&g_ctr, d);
        g_off[i] = s;
        g_cur[i] = s;
    }
}

__global__ void fill_csr_kernel(const int* __restrict__ src, const int* __restrict__ dst) {
    int e = blockIdx.x * blockDim.x + threadIdx.x;
    if (e < N_EDGES) {
        int d = dst[e];
        int p = atomicAdd(&g_cur[d], 1);
        g_csr_src[p] = src[e];
    }
}

// ==================== weight pre-conversion (fp32 -> tf32, k-permuted, usage order) ====
// row order r: r<64: W[64j+r] (m); r<128: F[64j+r-64] (gamma); r<192: F[64j+r] (beta).
// k-permutation within each 8-group: original i -> slot (i&3)*2 + (i>>2).

__global__ void prep_weights(const float* __restrict__ W,
                             const float* __restrict__ F,
                             int layer) {
    unsigned* dst = layer ? g_Bt2 : g_Bt1;
    int idx = blockIdx.x * blockDim.x + threadIdx.x;   // over 2*192*32 float4 groups
    if (idx >= 2 * 192 * 32) return;
    int j  = idx / (192 * 32);
    int r  = (idx >> 5) % 192;
    int c4 = (idx & 31) * 4;
    const float* srcRow;
    if (r < 64)       srcRow = W + (64 * j + r) * 128;
    else if (r < 128) srcRow = F + (64 * j + r - 64) * 128;
    else              srcRow = F + (64 * j + r) * 128;
    float4 v = *(const float4*)(srcRow + c4);
    unsigned* p = dst + (j * 192 + r) * 128 + ((c4 >> 3) << 3) + ((c4 & 4) ? 1 : 0);
    p[0] = f2tf32(v.x); p[2] = f2tf32(v.y); p[4] = f2tf32(v.z); p[6] = f2tf32(v.w);
}

__global__ void prep_wp(const float* __restrict__ Wp) {
    int idx = blockIdx.x * blockDim.x + threadIdx.x;   // over 64*32 float4 groups
    if (idx >= 64 * 32) return;
    float4 v = *(const float4*)(Wp + idx * 4);
    unsigned* p = g_Bp + idx * 4;
    p[0] = f2tf32(v.x); p[1] = f2tf32(v.y); p[2] = f2tf32(v.z); p[3] = f2tf32(v.w);
}

// ==================== fused FiLM GEMM (tf32 tc, M=128, 256 thr, 32x96 warp tile) =======
// 8 warps: wr = wid>>1 owns node rows [wr*32, +32), wc = wid&1 owns weight cols
// [wc*32, +32) of each of the 3 mats (m/gamma/beta). Per ks: 4 A-frag LDS.64 +
// 12 B-frag LDS.64 feeding 24 MMAs (B reused across the two 16-row fragments).

__global__ void film_gemm_fused(const float* __restrict__ Ain, int layer) {
    extern __shared__ unsigned smem[];
    unsigned* sA = smem;                   // 128*PADA (k-permuted)
    unsigned* sB = smem + 128 * PADA;      // 192*PADA (full-K panel of one j half)

    const float*    A  = layer ? g_h : Ain;
    const unsigned* Bt = layer ? g_Bt2 : g_Bt1;

    int tid  = threadIdx.x;     // 256
    int wid  = tid >> 5;
    int lane = tid & 31;
    int g    = lane >> 2;       // 0..7
    int tg   = lane & 3;        // 0..3
    int wr   = wid >> 1;        // 0..3 (32-row group)
    int wc   = wid & 1;         // 0..1 (32-col group per mat)
    int row0 = blockIdx.x * 128;

    // load A tile (128 rows x 128 K) as tf32, k-permuted, STS.128
    // each iteration handles one 8-group: slots 0..7 contiguous after permute
    for (int idx = tid; idx < 128 * 16; idx += 256) {
        int r  = idx >> 4;
        int c8 = (idx & 15) * 8;
        int grow = row0 + r;
        float4 v0, v1;
        if (grow < N_NODES) {
            v0 = *(const float4*)(A + grow * 128 + c8);
            v1 = *(const float4*)(A + grow * 128 + c8 + 4);
        } else {
            v0 = make_float4(0.f, 0.f, 0.f, 0.f);
            v1 = v0;
        }
        // permute: out[0]=in0 out[1]=in4 out[2]=in1 out[3]=in5 out[4]=in2 out[5]=in6 out[6]=in3 out[7]=in7
        uint4 q0 = make_uint4(f2tf32(v0.x), f2tf32(v1.x), f2tf32(v0.y), f2tf32(v1.y));
        uint4 q1 = make_uint4(f2tf32(v0.z), f2tf32(v1.z), f2tf32(v0.w), f2tf32(v1.w));
        unsigned* p = sA + r * PADA + c8;
        *(uint4*)(p)     = q0;
        *(uint4*)(p + 4) = q1;
    }

#pragma unroll
    for (int j = 0; j < 2; j++) {
        float acc[3][4][2][4];   // [mat][nt][row-frag][quad]
#pragma unroll
        for (int m = 0; m < 3; m++)
#pragma unroll
            for (int n = 0; n < 4; n++)
#pragma unroll
                for (int rf = 0; rf < 2; rf++)
#pragma unroll
                    for (int q = 0; q < 4; q++) acc[m][n][rf][q] = 0.f;

        __syncthreads();   // protect sB from previous j's readers (and A stores, j=0)
        // stage full-K weight panel for this j (already tf32 + permuted): raw uint4 copy
        for (int idx = tid; idx < 192 * 32; idx += 256) {
            int r  = idx >> 5;
            int cw = (idx & 31) * 4;
            uint4 v = *(const uint4*)(Bt + (j * 192 + r) * 128 + cw);
            *(uint4*)(sB + r * PADA + cw) = v;
        }
        __syncthreads();

        const unsigned* aW = sA + (wr * 32 + g) * PADA + 2 * tg;
        const unsigned* bW = sB + (wc * 32 + g) * PADA + 2 * tg;
#pragma unroll
        for (int ks = 0; ks < 16; ks++) {
            int k0 = ks * 8;
            uint2 a0Lo = *(const uint2*)(aW + k0);               // rows wr*32+g
            uint2 a0Hi = *(const uint2*)(aW + 8 * PADA + k0);    // +8
            uint2 a1Lo = *(const uint2*)(aW + 16 * PADA + k0);   // +16
            uint2 a1Hi = *(const uint2*)(aW + 24 * PADA + k0);   // +24
#pragma unroll
            for (int mat = 0; mat < 3; mat++) {
#pragma unroll
                for (int nt = 0; nt < 4; nt++) {
                    uint2 b = *(const uint2*)(bW + (mat * 64 + nt * 8) * PADA + k0);
                    mma_tf32(acc[mat][nt][0], a0Lo.x, a0Hi.x, a0Lo.y, a0Hi.y, b.x, b.y);
                    mma_tf32(acc[mat][nt][1], a1Lo.x, a1Hi.x, a1Lo.y, a1Hi.y, b.x, b.y);
                }
            }
        }

        // epilogue: msg = relu(gamma*m + beta) -> fp16
#pragma unroll
        for (int rf = 0; rf < 2; rf++) {
            int ra = row0 + wr * 32 + rf * 16 + g;
            int rb = ra + 8;
#pragma unroll
            for (int nt = 0; nt < 4; nt++) {
                int col = 64 * j + wc * 32 + nt * 8 + 2 * tg;
                const float* m_  = acc[0][nt][rf];
                const float* ga_ = acc[1][nt][rf];
                const float* be_ = acc[2][nt][rf];
                float v0 = fmaxf(fmaf(ga_[0], m_[0], be_[0]), 0.f);
                float v1 = fmaxf(fmaf(ga_[1], m_[1], be_[1]), 0.f);
                float v2 = fmaxf(fmaf(ga_[2], m_[2], be_[2]), 0.f);
                float v3 = fmaxf(fmaf(ga_[3], m_[3], be_[3]), 0.f);
                __half2 ha = __floats2half2_rn(v0, v1);
                __half2 hb = __floats2half2_rn(v2, v3);
                if (ra < N_NODES) g_msg[ra * 64 + (col >> 1)] = ha;
                if (rb < N_NODES) g_msg[rb * 64 + (col >> 1)] = hb;
            }
        }
    }
}

// ==================== output head: sigmoid(g_h @ Wp.T + bp) ====================

__global__ void gemm_out_tc(const float* __restrict__ bp,
                            float* __restrict__ out) {
    extern __shared__ unsigned smem[];
    unsigned* sA = smem;                 // 64*PADA
    unsigned* sB = smem + 64 * PADA;     // 64*PADA

    int tid  = threadIdx.x;
    int wid  = tid >> 5;
    int lane = tid & 31;
    int g    = lane >> 2;
    int tg   = lane & 3;
    int wr   = wid >> 1;
    int wc   = wid & 1;
    int row0 = blockIdx.x * 64;

    for (int idx = tid; idx < 64 * 32; idx += 256) {
        int r = idx >> 5;
        int c4 = (idx & 31) * 4;
        int grow = row0 + r;
        float4 v = (grow < N_NODES) ? *(const float4*)(g_h + grow * 128 + c4)
                                    : make_float4(0.f, 0.f, 0.f, 0.f);
        unsigned* p = sA + r * PADA + c4;
        p[0] = f2tf32(v.x); p[1] = f2tf32(v.y); p[2] = f2tf32(v.z); p[3] = f2tf32(v.w);
    }
    for (int idx = tid; idx < 64 * 32; idx += 256) {
        int r = idx >> 5;
        int c4 = (idx & 31) * 4;
        uint4 v = *(const uint4*)(g_Bp + r * 128 + c4);
        *(uint4*)(sB + r * PADA + c4) = v;
    }
    __syncthreads();

    float acc[4][4];
#pragma unroll
    for (int n = 0; n < 4; n++)
#pragma unroll
        for (int q = 0; q < 4; q++) acc[n][q] = 0.f;

    const unsigned* aW = sA + (wr * 16 + g) * PADA + tg;
#pragma unroll
    for (int ks = 0; ks < 16; ks++) {
        int k0 = ks * 8;
        unsigned a0 = aW[k0];
        unsigned a1 = aW[8 * PADA + k0];
        unsigned a2 = aW[k0 + 4];
        unsigned a3 = aW[8 * PADA + k0 + 4];
#pragma unroll
        for (int nt = 0; nt < 4; nt++) {
            const unsigned* bptr = sB + (wc * 32 + nt * 8 + g) * PADA + k0 + tg;
            mma_tf32(acc[nt], a0, a1, a2, a3, bptr[0], bptr[4]);
        }
    }

    int ra = row0 + wr * 16 + g;
    int rb = ra + 8;
#pragma unroll
    for (int nt = 0; nt < 4; nt++) {
        int col = wc * 32 + nt * 8 + 2 * tg;
        float bpv0 = bp[col], bpv1 = bp[col + 1];
        float v0 = 1.f / (1.f + __expf(-(acc[nt][0] + bpv0)));
        float v1 = 1.f / (1.f + __expf(-(acc[nt][1] + bpv1)));
        float v2 = 1.f / (1.f + __expf(-(acc[nt][2] + bpv0)));
        float v3 = 1.f / (1.f + __expf(-(acc[nt][3] + bpv1)));
        if (ra < N_NODES) *(float2*)&out[ra * 64 + col] = make_float2(v0, v1);
        if (rb < N_NODES) *(float2*)&out[rb * 64 + col] = make_float2(v2, v3);
    }
}

// ==================== aggregate + layernorm (fused, warp per node, fp16 gather) ========

__global__ void aggregate_ln_kernel(const float* __restrict__ gam,
                                    const float* __restrict__ bet) {
    int gw = (blockIdx.x * blockDim.x + threadIdx.x) >> 5;
    int lane = threadIdx.x & 31;
    if (gw >= N_NODES) return;

    int s0 = g_off[gw], s1 = s0 + g_deg[gw];
    const uint2* msg2 = (const uint2*)g_msg;   // 32 uint2 (= 4 halves each) per node row

    float4 acc0 = make_float4(0.f, 0.f, 0.f, 0.f);
    float4 acc1 = make_float4(0.f, 0.f, 0.f, 0.f);
    int i = s0;
    for (; i + 2 <= s1; i += 2) {
        int sa = __ldg(&g_csr_src[i]);
        int sb = __ldg(&g_csr_src[i + 1]);
        uint2 ua = __ldg(&msg2[sa * 32 + lane]);
        uint2 ub = __ldg(&msg2[sb * 32 + lane]);
        float2 a01 = __half22float2(*(__half2*)&ua.x);
        float2 a23 = __half22float2(*(__half2*)&ua.y);
        float2 b01 = __half22float2(*(__half2*)&ub.x);
        float2 b23 = __half22float2(*(__half2*)&ub.y);
        acc0.x += a01.x; acc0.y += a01.y; acc0.z += a23.x; acc0.w += a23.y;
        acc1.x += b01.x; acc1.y += b01.y; acc1.z += b23.x; acc1.w += b23.y;
    }
    if (i < s1) {
        int sa = __ldg(&g_csr_src[i]);
        uint2 ua = __ldg(&msg2[sa * 32 + lane]);
        float2 a01 = __half22float2(*(__half2*)&ua.x);
        float2 a23 = __half22float2(*(__half2*)&ua.y);
        acc0.x += a01.x; acc0.y += a01.y; acc0.z += a23.x; acc0.w += a23.y;
    }
    float4 acc = make_float4(acc0.x + acc1.x, acc0.y + acc1.y,
                             acc0.z + acc1.z, acc0.w + acc1.w);

    float sum = acc.x + acc.y + acc.z + acc.w;
    float sq  = acc.x * acc.x + acc.y * acc.y + acc.z * acc.z + acc.w * acc.w;
#pragma unroll
    for (int o = 16; o > 0; o >>= 1) {
        sum += __shfl_xor_sync(0xffffffffu, sum, o);
        sq  += __shfl_xor_sync(0xffffffffu, sq,  o);
    }
    float mu  = sum * (1.f / 128.f);
    float var = sq * (1.f / 128.f) - mu * mu;
    float rs  = rsqrtf(var + 1e-5f);

    float4 gv = *(const float4*)&gam[lane * 4];
    float4 bv = *(const float4*)&bet[lane * 4];
    float4 o;
    o.x = (acc.x - mu) * rs * gv.x + bv.x;
    o.y = (acc.y - mu) * rs * gv.y + bv.y;
    o.z = (acc.z - mu) * rs * gv.z + bv.z;
    o.w = (acc.w - mu) * rs * gv.w + bv.w;
    *(float4*)&g_h[gw * 128 + lane * 4] = o;
}

// ============================ launch ============================

extern "C" void kernel_launch(void* const* d_in, const int* in_sizes, int n_in,
                              void* d_out, int out_size) {
    const float* features = (const float*)d_in[0];
    const int*   src      = (const int*)  d_in[1];
    const int*   dst      = (const int*)  d_in[2];
    const float* W1       = (const float*)d_in[3];
    const float* F1       = (const float*)d_in[4];
    const float* g1       = (const float*)d_in[5];
    const float* b1       = (const float*)d_in[6];
    const float* W2       = (const float*)d_in[7];
    const float* F2       = (const float*)d_in[8];
    const float* g2       = (const float*)d_in[9];
    const float* b2       = (const float*)d_in[10];
    const float* Wp       = (const float*)d_in[11];
    const float* bp       = (const float*)d_in[12];
    float* out = (float*)d_out;

    // persistent side stream + events (host resources, created once)
    static cudaStream_t s_side = nullptr;
    static cudaEvent_t  ev_fork = nullptr, ev_join = nullptr;
    if (s_side == nullptr) {
        cudaStreamCreateWithFlags(&s_side, cudaStreamNonBlocking);
        cudaEventCreateWithFlags(&ev_fork, cudaEventDisableTiming);
        cudaEventCreateWithFlags(&ev_join, cudaEventDisableTiming);
    }

    const int smem_film = (128 * PADA + 192 * PADA) * 4;   // 174080 B
    const int smem_out  = (64 * PADA + 64 * PADA) * 4;     // 69632 B
    cudaFuncSetAttribute(film_gemm_fused, cudaFuncAttributeMaxDynamicSharedMemorySize, smem_film);
    cudaFuncSetAttribute(gemm_out_tc,     cudaFuncAttributeMaxDynamicSharedMemorySize, smem_out);

    dim3 film_grid((N_NODES + 127) / 128);
    dim3 agg_grid((N_NODES + 7) / 8);

    // fork side branch off the capture-origin stream
    cudaEventRecord(ev_fork, 0);
    cudaStreamWaitEvent(s_side, ev_fork, 0);

    // branch B (side stream): CSR build + layer-2/head weight prep
    zero_deg_kernel<<<(N_NODES + 255) / 256, 256, 0, s_side>>>();
    hist_kernel<<<(N_EDGES + 255) / 256, 256, 0, s_side>>>(dst);
    offsets_kernel<<<(N_NODES + 255) / 256, 256, 0, s_side>>>();
    fill_csr_kernel<<<(N_EDGES + 255) / 256, 256, 0, s_side>>>(src, dst);
    prep_weights<<<(2 * 192 * 32 + 255) / 256, 256, 0, s_side>>>(W2, F2, 1);
    prep_wp<<<(64 * 32 + 255) / 256, 256, 0, s_side>>>(Wp);
    cudaEventRecord(ev_join, s_side);

    // branch A (origin stream): layer-1 prep + GEMM
    prep_weights<<<(2 * 192 * 32 + 255) / 256, 256>>>(W1, F1, 0);
    film_gemm_fused<<<film_grid, 256, smem_film>>>(features, 0);

    // join: aggregation needs CSR + msg
    cudaStreamWaitEvent(0, ev_join, 0);
    aggregate_ln_kernel<<<agg_grid, 256>>>(g1, b1);

    // layer 2
    film_gemm_fused<<<film_grid, 256, smem_film>>>(nullptr, 1);
    aggregate_ln_kernel<<<agg_grid, 256>>>(g2, b2);

    // output head
    gemm_out_tc<<<(N_NODES + 63) / 64, 256, smem_out>>>(bp, out);
}

// round 8
// speedup vs baseline: 1.0846x; 1.0846x over previous
#include <cuda_runtime.h>
#include <cuda_fp16.h>

#define N_NODES 50000
#define N_EDGES 600000
#define DIM 128
#define OUTD 64

#define PADA 136   // words per row (k-stride); 136 mod 32 = 8 -> conflict-free LDS.64

// ---- scratch (static device globals; no runtime allocation) ----
__device__ __half2   g_msg[N_NODES * 64];   // fp16 messages (128 per node)
__device__ float     g_h[N_NODES * DIM];
__device__ int       g_deg[N_NODES];
__device__ int       g_off[N_NODES];
__device__ int       g_cur[N_NODES];
__device__ int       g_ctr;
__device__ int       g_csr_src[N_EDGES];
__device__ unsigned  g_Bt1[2 * 192 * 128];  // layer-1 weights, tf32, k-permuted, usage order
__device__ unsigned  g_Bt2[2 * 192 * 128];  // layer-2 weights
__device__ unsigned  g_Bp[64 * 128];        // Wp, tf32 (unpermuted)

// ============================ helpers ============================

__device__ __forceinline__ unsigned f2tf32(float f) {
    unsigned u;
    asm("cvt.rna.tf32.f32 %0, %1;" : "=r"(u) : "f"(f));
    return u;
}

__device__ __forceinline__ void mma_tf32(float* c,
                                         unsigned a0, unsigned a1, unsigned a2, unsigned a3,
                                         unsigned b0, unsigned b1) {
    asm volatile(
        "mma.sync.aligned.m16n8k8.row.col.f32.tf32.tf32.f32 "
        "{%0,%1,%2,%3}, {%4,%5,%6,%7}, {%8,%9}, {%0,%1,%2,%3};"
        : "+f"(c[0]), "+f"(c[1]), "+f"(c[2]), "+f"(c[3])
        : "r"(a0), "r"(a1), "r"(a2), "r"(a3), "r"(b0), "r"(b1));
}

// ============================ CSR build ============================

__global__ void zero_deg_kernel() {
    int i = blockIdx.x * blockDim.x + threadIdx.x;
    if (i < N_NODES) g_deg[i] = 0;
    if (i == 0) g_ctr = 0;
}

__global__ void hist_kernel(const int* __restrict__ dst) {
    int e = blockIdx.x * blockDim.x + threadIdx.x;
    if (e < N_EDGES) atomicAdd(&g_deg[dst[e]], 1);
}

// unordered disjoint range claim (aggregation is order-agnostic)
__global__ void offsets_kernel() {
    int i = blockIdx.x * blockDim.x + threadIdx.x;
    if (i < N_NODES) {
        int d = g_deg[i];
        int s = atomicAdd(&g_ctr, d);
        g_off[i] = s;
        g_cur[i] = s;
    }
}

__global__ void fill_csr_kernel(const int* __restrict__ src, const int* __restrict__ dst) {
    int e = blockIdx.x * blockDim.x + threadIdx.x;
    if (e < N_EDGES) {
        int d = dst[e];
        int p = atomicAdd(&g_cur[d], 1);
        g_csr_src[p] = src[e];
    }
}

// ==================== weight pre-conversion (fp32 -> tf32, k-permuted, usage order) ====
// row order r: r<64: W[64j+r] (m); r<128: F[64j+r-64] (gamma); r<192: F[64j+r] (beta).
// k-permutation within each 8-group: original i -> slot (i&3)*2 + (i>>2).

__global__ void prep_weights(const float* __restrict__ W,
                             const float* __restrict__ F,
                             int layer) {
    unsigned* dst = layer ? g_Bt2 : g_Bt1;
    int idx = blockIdx.x * blockDim.x + threadIdx.x;   // over 2*192*32 float4 groups
    if (idx >= 2 * 192 * 32) return;
    int j  = idx / (192 * 32);
    int r  = (idx >> 5) % 192;
    int c4 = (idx & 31) * 4;
    const float* srcRow;
    if (r < 64)       srcRow = W + (64 * j + r) * 128;
    else if (r < 128) srcRow = F + (64 * j + r - 64) * 128;
    else              srcRow = F + (64 * j + r) * 128;
    float4 v = *(const float4*)(srcRow + c4);
    unsigned* p = dst + (j * 192 + r) * 128 + ((c4 >> 3) << 3) + ((c4 & 4) ? 1 : 0);
    p[0] = f2tf32(v.x); p[2] = f2tf32(v.y); p[4] = f2tf32(v.z); p[6] = f2tf32(v.w);
}

__global__ void prep_wp(const float* __restrict__ Wp) {
    int idx = blockIdx.x * blockDim.x + threadIdx.x;   // over 64*32 float4 groups
    if (idx >= 64 * 32) return;
    float4 v = *(const float4*)(Wp + idx * 4);
    unsigned* p = g_Bp + idx * 4;
    p[0] = f2tf32(v.x); p[1] = f2tf32(v.y); p[2] = f2tf32(v.z); p[3] = f2tf32(v.w);
}

// ==================== fused FiLM GEMM (tf32 tc, M=128, 512 thr, 32x48 warp tile) =======
// 16 warps: wr = wid>>2 owns node rows [wr*32, +32); wc = wid&3 owns weight cols
// [wc*16, +16) of each of the 3 mats (m/gamma/beta). Per ks: 4 A-frag + 6 B-frag
// LDS.64 feeding 12 MMAs (B reused across the two 16-row fragments) = 0.83 LDS/MMA.

__global__ void film_gemm_fused(const float* __restrict__ Ain, int layer) {
    extern __shared__ unsigned smem[];
    unsigned* sA = smem;                   // 128*PADA (k-permuted)
    unsigned* sB = smem + 128 * PADA;      // 192*PADA (full-K panel of one j half)

    const float*    A  = layer ? g_h : Ain;
    const unsigned* Bt = layer ? g_Bt2 : g_Bt1;

    int tid  = threadIdx.x;     // 512
    int wid  = tid >> 5;
    int lane = tid & 31;
    int g    = lane >> 2;       // 0..7
    int tg   = lane & 3;        // 0..3
    int wr   = wid >> 2;        // 0..3 (32-row group)
    int wc   = wid & 3;         // 0..3 (16-col group per mat)
    int row0 = blockIdx.x * 128;

    // load A tile (128 rows x 128 K) as tf32, k-permuted, STS.128
    for (int idx = tid; idx < 128 * 16; idx += 512) {
        int r  = idx >> 4;
        int c8 = (idx & 15) * 8;
        int grow = row0 + r;
        float4 v0, v1;
        if (grow < N_NODES) {
            v0 = *(const float4*)(A + grow * 128 + c8);
            v1 = *(const float4*)(A + grow * 128 + c8 + 4);
        } else {
            v0 = make_float4(0.f, 0.f, 0.f, 0.f);
            v1 = v0;
        }
        uint4 q0 = make_uint4(f2tf32(v0.x), f2tf32(v1.x), f2tf32(v0.y), f2tf32(v1.y));
        uint4 q1 = make_uint4(f2tf32(v0.z), f2tf32(v1.z), f2tf32(v0.w), f2tf32(v1.w));
        unsigned* p = sA + r * PADA + c8;
        *(uint4*)(p)     = q0;
        *(uint4*)(p + 4) = q1;
    }

#pragma unroll
    for (int j = 0; j < 2; j++) {
        float acc[3][2][2][4];   // [mat][nt][row-frag][quad]
#pragma unroll
        for (int m = 0; m < 3; m++)
#pragma unroll
            for (int n = 0; n < 2; n++)
#pragma unroll
                for (int rf = 0; rf < 2; rf++)
#pragma unroll
                    for (int q = 0; q < 4; q++) acc[m][n][rf][q] = 0.f;

        __syncthreads();   // protect sB from previous j's readers (and A stores, j=0)
        // stage full-K weight panel for this j (already tf32 + permuted): raw uint4 copy
        for (int idx = tid; idx < 192 * 32; idx += 512) {
            int r  = idx >> 5;
            int cw = (idx & 31) * 4;
            uint4 v = *(const uint4*)(Bt + (j * 192 + r) * 128 + cw);
            *(uint4*)(sB + r * PADA + cw) = v;
        }
        __syncthreads();

        const unsigned* aW = sA + (wr * 32 + g) * PADA + 2 * tg;
        const unsigned* bW = sB + (wc * 16 + g) * PADA + 2 * tg;
#pragma unroll
        for (int ks = 0; ks < 16; ks++) {
            int k0 = ks * 8;
            uint2 a0Lo = *(const uint2*)(aW + k0);               // rows wr*32+g
            uint2 a0Hi = *(const uint2*)(aW + 8 * PADA + k0);    // +8
            uint2 a1Lo = *(const uint2*)(aW + 16 * PADA + k0);   // +16
            uint2 a1Hi = *(const uint2*)(aW + 24 * PADA + k0);   // +24
#pragma unroll
            for (int mat = 0; mat < 3; mat++) {
#pragma unroll
                for (int nt = 0; nt < 2; nt++) {
                    uint2 b = *(const uint2*)(bW + (mat * 64 + nt * 8) * PADA + k0);
                    mma_tf32(acc[mat][nt][0], a0Lo.x, a0Hi.x, a0Lo.y, a0Hi.y, b.x, b.y);
                    mma_tf32(acc[mat][nt][1], a1Lo.x, a1Hi.x, a1Lo.y, a1Hi.y, b.x, b.y);
                }
            }
        }

        // epilogue: msg = relu(gamma*m + beta) -> fp16
#pragma unroll
        for (int rf = 0; rf < 2; rf++) {
            int ra = row0 + wr * 32 + rf * 16 + g;
            int rb = ra + 8;
#pragma unroll
            for (int nt = 0; nt < 2; nt++) {
                int col = 64 * j + wc * 16 + nt * 8 + 2 * tg;
                const float* m_  = acc[0][nt][rf];
                const float* ga_ = acc[1][nt][rf];
                const float* be_ = acc[2][nt][rf];
                float v0 = fmaxf(fmaf(ga_[0], m_[0], be_[0]), 0.f);
                float v1 = fmaxf(fmaf(ga_[1], m_[1], be_[1]), 0.f);
                float v2 = fmaxf(fmaf(ga_[2], m_[2], be_[2]), 0.f);
                float v3 = fmaxf(fmaf(ga_[3], m_[3], be_[3]), 0.f);
                __half2 ha = __floats2half2_rn(v0, v1);
                __half2 hb = __floats2half2_rn(v2, v3);
                if (ra < N_NODES) g_msg[ra * 64 + (col >> 1)] = ha;
                if (rb < N_NODES) g_msg[rb * 64 + (col >> 1)] = hb;
            }
        }
    }
}

// ==================== output head: sigmoid(g_h @ Wp.T + bp) ====================

__global__ void gemm_out_tc(const float* __restrict__ bp,
                            float* __restrict__ out) {
    extern __shared__ unsigned smem[];
    unsigned* sA = smem;                 // 64*PADA
    unsigned* sB = smem + 64 * PADA;     // 64*PADA

    int tid  = threadIdx.x;
    int wid  = tid >> 5;
    int lane = tid & 31;
    int g    = lane >> 2;
    int tg   = lane & 3;
    int wr   = wid >> 1;
    int wc   = wid & 1;
    int row0 = blockIdx.x * 64;

    for (int idx = tid; idx < 64 * 32; idx += 256) {
        int r = idx >> 5;
        int c4 = (idx & 31) * 4;
        int grow = row0 + r;
        float4 v = (grow < N_NODES) ? *(const float4*)(g_h + grow * 128 + c4)
                                    : make_float4(0.f, 0.f, 0.f, 0.f);
        unsigned* p = sA + r * PADA + c4;
        p[0] = f2tf32(v.x); p[1] = f2tf32(v.y); p[2] = f2tf32(v.z); p[3] = f2tf32(v.w);
    }
    for (int idx = tid; idx < 64 * 32; idx += 256) {
        int r = idx >> 5;
        int c4 = (idx & 31) * 4;
        uint4 v = *(const uint4*)(g_Bp + r * 128 + c4);
        *(uint4*)(sB + r * PADA + c4) = v;
    }
    __syncthreads();

    float acc[4][4];
#pragma unroll
    for (int n = 0; n < 4; n++)
#pragma unroll
        for (int q = 0; q < 4; q++) acc[n][q] = 0.f;

    const unsigned* aW = sA + (wr * 16 + g) * PADA + tg;
#pragma unroll
    for (int ks = 0; ks < 16; ks++) {
        int k0 = ks * 8;
        unsigned a0 = aW[k0];
        unsigned a1 = aW[8 * PADA + k0];
        unsigned a2 = aW[k0 + 4];
        unsigned a3 = aW[8 * PADA + k0 + 4];
#pragma unroll
        for (int nt = 0; nt < 4; nt++) {
            const unsigned* bptr = sB + (wc * 32 + nt * 8 + g) * PADA + k0 + tg;
            mma_tf32(acc[nt], a0, a1, a2, a3, bptr[0], bptr[4]);
        }
    }

    int ra = row0 + wr * 16 + g;
    int rb = ra + 8;
#pragma unroll
    for (int nt = 0; nt < 4; nt++) {
        int col = wc * 32 + nt * 8 + 2 * tg;
        float bpv0 = bp[col], bpv1 = bp[col + 1];
        float v0 = 1.f / (1.f + __expf(-(acc[nt][0] + bpv0)));
        float v1 = 1.f / (1.f + __expf(-(acc[nt][1] + bpv1)));
        float v2 = 1.f / (1.f + __expf(-(acc[nt][2] + bpv0)));
        float v3 = 1.f / (1.f + __expf(-(acc[nt][3] + bpv1)));
        if (ra < N_NODES) *(float2*)&out[ra * 64 + col] = make_float2(v0, v1);
        if (rb < N_NODES) *(float2*)&out[rb * 64 + col] = make_float2(v2, v3);
    }
}

// ==================== aggregate + layernorm (fused, warp per node, fp16 gather) ========

__global__ void aggregate_ln_kernel(const float* __restrict__ gam,
                                    const float* __restrict__ bet) {
    int gw = (blockIdx.x * blockDim.x + threadIdx.x) >> 5;
    int lane = threadIdx.x & 31;
    if (gw >= N_NODES) return;

    int s0 = g_off[gw], s1 = s0 + g_deg[gw];
    const uint2* msg2 = (const uint2*)g_msg;   // 32 uint2 (= 4 halves each) per node row

    float4 acc0 = make_float4(0.f, 0.f, 0.f, 0.f);
    float4 acc1 = make_float4(0.f, 0.f, 0.f, 0.f);
    int i = s0;
    for (; i + 2 <= s1; i += 2) {
        int sa = __ldg(&g_csr_src[i]);
        int sb = __ldg(&g_csr_src[i + 1]);
        uint2 ua = __ldg(&msg2[sa * 32 + lane]);
        uint2 ub = __ldg(&msg2[sb * 32 + lane]);
        float2 a01 = __half22float2(*(__half2*)&ua.x);
        float2 a23 = __half22float2(*(__half2*)&ua.y);
        float2 b01 = __half22float2(*(__half2*)&ub.x);
        float2 b23 = __half22float2(*(__half2*)&ub.y);
        acc0.x += a01.x; acc0.y += a01.y; acc0.z += a23.x; acc0.w += a23.y;
        acc1.x += b01.x; acc1.y += b01.y; acc1.z += b23.x; acc1.w += b23.y;
    }
    if (i < s1) {
        int sa = __ldg(&g_csr_src[i]);
        uint2 ua = __ldg(&msg2[sa * 32 + lane]);
        float2 a01 = __half22float2(*(__half2*)&ua.x);
        float2 a23 = __half22float2(*(__half2*)&ua.y);
        acc0.x += a01.x; acc0.y += a01.y; acc0.z += a23.x; acc0.w += a23.y;
    }
    float4 acc = make_float4(acc0.x + acc1.x, acc0.y + acc1.y,
                             acc0.z + acc1.z, acc0.w + acc1.w);

    float sum = acc.x + acc.y + acc.z + acc.w;
    float sq  = acc.x * acc.x + acc.y * acc.y + acc.z * acc.z + acc.w * acc.w;
#pragma unroll
    for (int o = 16; o > 0; o >>= 1) {
        sum += __shfl_xor_sync(0xffffffffu, sum, o);
        sq  += __shfl_xor_sync(0xffffffffu, sq,  o);
    }
    float mu  = sum * (1.f / 128.f);
    float var = sq * (1.f / 128.f) - mu * mu;
    float rs  = rsqrtf(var + 1e-5f);

    float4 gv = *(const float4*)&gam[lane * 4];
    float4 bv = *(const float4*)&bet[lane * 4];
    float4 o;
    o.x = (acc.x - mu) * rs * gv.x + bv.x;
    o.y = (acc.y - mu) * rs * gv.y + bv.y;
    o.z = (acc.z - mu) * rs * gv.z + bv.z;
    o.w = (acc.w - mu) * rs * gv.w + bv.w;
    *(float4*)&g_h[gw * 128 + lane * 4] = o;
}

// ============================ launch ============================

extern "C" void kernel_launch(void* const* d_in, const int* in_sizes, int n_in,
                              void* d_out, int out_size) {
    const float* features = (const float*)d_in[0];
    const int*   src      = (const int*)  d_in[1];
    const int*   dst      = (const int*)  d_in[2];
    const float* W1       = (const float*)d_in[3];
    const float* F1       = (const float*)d_in[4];
    const float* g1       = (const float*)d_in[5];
    const float* b1       = (const float*)d_in[6];
    const float* W2       = (const float*)d_in[7];
    const float* F2       = (const float*)d_in[8];
    const float* g2       = (const float*)d_in[9];
    const float* b2       = (const float*)d_in[10];
    const float* Wp       = (const float*)d_in[11];
    const float* bp       = (const float*)d_in[12];
    float* out = (float*)d_out;

    // persistent side stream + events (host resources, created once)
    static cudaStream_t s_side = nullptr;
    static cudaEvent_t  ev_fork = nullptr, ev_join = nullptr;
    if (s_side == nullptr) {
        cudaStreamCreateWithFlags(&s_side, cudaStreamNonBlocking);
        cudaEventCreateWithFlags(&ev_fork, cudaEventDisableTiming);
        cudaEventCreateWithFlags(&ev_join, cudaEventDisableTiming);
    }

    const int smem_film = (128 * PADA + 192 * PADA) * 4;   // 174080 B
    const int smem_out  = (64 * PADA + 64 * PADA) * 4;     // 69632 B
    cudaFuncSetAttribute(film_gemm_fused, cudaFuncAttributeMaxDynamicSharedMemorySize, smem_film);
    cudaFuncSetAttribute(gemm_out_tc,     cudaFuncAttributeMaxDynamicSharedMemorySize, smem_out);

    dim3 film_grid((N_NODES + 127) / 128);
    dim3 agg_grid((N_NODES + 7) / 8);

    // fork side branch off the capture-origin stream
    cudaEventRecord(ev_fork, 0);
    cudaStreamWaitEvent(s_side, ev_fork, 0);

    // branch B (side stream): CSR build + layer-2/head weight prep
    zero_deg_kernel<<<(N_NODES + 255) / 256, 256, 0, s_side>>>();
    hist_kernel<<<(N_EDGES + 255) / 256, 256, 0, s_side>>>(dst);
    offsets_kernel<<<(N_NODES + 255) / 256, 256, 0, s_side>>>();
    fill_csr_kernel<<<(N_EDGES + 255) / 256, 256, 0, s_side>>>(src, dst);
    prep_weights<<<(2 * 192 * 32 + 255) / 256, 256, 0, s_side>>>(W2, F2, 1);
    prep_wp<<<(64 * 32 + 255) / 256, 256, 0, s_side>>>(Wp);
    cudaEventRecord(ev_join, s_side);

    // branch A (origin stream): layer-1 prep + GEMM
    prep_weights<<<(2 * 192 * 32 + 255) / 256, 256>>>(W1, F1, 0);
    film_gemm_fused<<<film_grid, 512, smem_film>>>(features, 0);

    // join: aggregation needs CSR + msg
    cudaStreamWaitEvent(0, ev_join, 0);
    aggregate_ln_kernel<<<agg_grid, 256>>>(g1, b1);

    // layer 2
    film_gemm_fused<<<film_grid, 512, smem_film>>>(nullptr, 1);
    aggregate_ln_kernel<<<agg_grid, 256>>>(g2, b2);

    // output head
    gemm_out_tc<<<(N_NODES + 63) / 64, 256, smem_out>>>(bp, out);
}